// round 5
// baseline (speedup 1.0000x reference)
#include <cuda_runtime.h>
#include <math.h>

// Problem constants
#define Bq   2
#define Sq   2048
#define Eq   1024
#define Hq   16
#define QKVq 1152    // (16 + 2*1) * 64

// Scratch (device globals — no runtime allocation allowed)
__device__ unsigned g_q[(size_t)Bq * Sq * Eq];       // tf32, roped, scaled: [b*S+s][h*64+d]
__device__ unsigned g_k[(size_t)Bq * Sq * 64];       // tf32, roped
__device__ unsigned g_v[(size_t)Bq * Sq * 64];       // tf32
__device__ unsigned g_attn[(size_t)Bq * Sq * Eq];    // attention out (tf32)
__device__ float    g_cos[Sq * 32];
__device__ float    g_sin[Sq * 32];

// ---------------------------------------------------------------------------
__device__ __forceinline__ unsigned f2tf32(float x) {
    unsigned r;
    asm("cvt.rna.tf32.f32 %0, %1;" : "=r"(r) : "f"(x));
    return r;
}

// Round raw fp32 bits to nearest at the tf32 cutoff (bit 13). mma ignores
// bits [12:0], so for already-tf32 values this is a no-op on the math.
__device__ __forceinline__ unsigned rnd13(unsigned u) { return u + 0x1000u; }

__device__ __forceinline__ void mma_tf32(float* d, const unsigned* a,
                                         unsigned b0, unsigned b1) {
    asm volatile(
        "mma.sync.aligned.m16n8k8.row.col.f32.tf32.tf32.f32 "
        "{%0,%1,%2,%3}, {%4,%5,%6,%7}, {%8,%9}, {%0,%1,%2,%3};\n"
        : "+f"(d[0]), "+f"(d[1]), "+f"(d[2]), "+f"(d[3])
        : "r"(a[0]), "r"(a[1]), "r"(a[2]), "r"(a[3]), "r"(b0), "r"(b1));
}

#define CP16(dst, src) asm volatile("cp.async.cg.shared.global [%0], [%1], 16;\n" :: "r"(dst), "l"(src))
#define CPC            asm volatile("cp.async.commit_group;\n")
#define CPW(n)         asm volatile("cp.async.wait_group %0;\n" :: "n"(n))

// ---------------------------------------------------------------------------
// RoPE tables
// ---------------------------------------------------------------------------
__global__ void rope_tables_kernel() {
    int idx = blockIdx.x * blockDim.x + threadIdx.x;
    if (idx >= Sq * 32) return;
    int s = idx >> 5;
    int i = idx & 31;
    double inv = exp(-(2.0 * i / 64.0) * log(10000.0));
    double ang = (double)s * inv;
    g_cos[idx] = (float)cos(ang);
    g_sin[idx] = (float)sin(ang);
}

// ---------------------------------------------------------------------------
// Double-buffered tf32 tensor GEMM (NT): C = A * W^T + bias
// Block 128x128, BK=32, 256 thr (8 warps: 2m x 4n), warp tile 64x32.
// Single barrier per K-step: wait -> barrier -> issue-next -> compute.
// RND_A: round A fragments (raw fp32 input). B (weights) always rounded.
// ROPE=true: epilogue applies bias + RoPE + scale, writes tf32 q/k/v.
// ---------------------------------------------------------------------------
template <int N, bool ROPE, bool RND_A>
__device__ __forceinline__ void gemm_body(const unsigned* __restrict__ A,
                                          const unsigned* __restrict__ W,
                                          const float* __restrict__ bias,
                                          float* __restrict__ C) {
    extern __shared__ unsigned sm[];
    unsigned* sA = sm;                 // [2][128][36]
    unsigned* sB = sm + 2 * 128 * 36;  // [2][128][36]

    const int tid  = threadIdx.x;
    const int warp = tid >> 5;
    const int lane = tid & 31;
    const int g    = lane >> 2;
    const int tq   = lane & 3;
    const int wm   = (warp & 1) * 64;
    const int wn   = (warp >> 1) * 32;
    const int bm   = blockIdx.y * 128;
    const int bn   = blockIdx.x * 128;

    unsigned smb  = (unsigned)__cvta_generic_to_shared(sm);
    unsigned sA_b = smb;
    unsigned sB_b = smb + 2u * 128u * 36u * 4u;

    float acc[4][4][4];
#pragma unroll
    for (int mt = 0; mt < 4; mt++)
#pragma unroll
        for (int nt = 0; nt < 4; nt++)
#pragma unroll
            for (int e = 0; e < 4; e++) acc[mt][nt][e] = 0.f;

    // prologue: stage buf 0
#pragma unroll
    for (int i = 0; i < 4; i++) {
        int c = tid + i * 256;
        int r = c >> 3, col = (c & 7) * 4;
        CP16(sA_b + (unsigned)(r * 36 + col) * 4u, A + (size_t)(bm + r) * Eq + col);
        CP16(sB_b + (unsigned)(r * 36 + col) * 4u, W + (size_t)(bn + r) * Eq + col);
    }
    CPC;

    for (int k0 = 0; k0 < Eq; k0 += 32) {
        int buf = (k0 >> 5) & 1;
        CPW(0);
        __syncthreads();

        if (k0 + 32 < Eq) {
            unsigned da = sA_b + (unsigned)((buf ^ 1) * 4608) * 4u;
            unsigned db = sB_b + (unsigned)((buf ^ 1) * 4608) * 4u;
#pragma unroll
            for (int i = 0; i < 4; i++) {
                int c = tid + i * 256;
                int r = c >> 3, col = (c & 7) * 4;
                CP16(da + (unsigned)(r * 36 + col) * 4u, A + (size_t)(bm + r) * Eq + k0 + 32 + col);
                CP16(db + (unsigned)(r * 36 + col) * 4u, W + (size_t)(bn + r) * Eq + k0 + 32 + col);
            }
            CPC;
        }

        const unsigned* As_ = sA + buf * 4608;
        const unsigned* Bs_ = sB + buf * 4608;
#pragma unroll
        for (int ks = 0; ks < 4; ks++) {
            unsigned a[4][4];
#pragma unroll
            for (int mt = 0; mt < 4; mt++) {
                int r = wm + mt * 16 + g;
                a[mt][0] = As_[r * 36 + ks * 8 + tq];
                a[mt][1] = As_[(r + 8) * 36 + ks * 8 + tq];
                a[mt][2] = As_[r * 36 + ks * 8 + tq + 4];
                a[mt][3] = As_[(r + 8) * 36 + ks * 8 + tq + 4];
                if (RND_A) {
                    a[mt][0] = rnd13(a[mt][0]); a[mt][1] = rnd13(a[mt][1]);
                    a[mt][2] = rnd13(a[mt][2]); a[mt][3] = rnd13(a[mt][3]);
                }
            }
#pragma unroll
            for (int nt = 0; nt < 4; nt++) {
                unsigned b0 = rnd13(Bs_[(wn + nt * 8 + g) * 36 + ks * 8 + tq]);
                unsigned b1 = rnd13(Bs_[(wn + nt * 8 + g) * 36 + ks * 8 + tq + 4]);
#pragma unroll
                for (int mt = 0; mt < 4; mt++)
                    mma_tf32(acc[mt][nt], a[mt], b0, b1);
            }
        }
    }

    // Epilogue
#pragma unroll
    for (int mt = 0; mt < 4; mt++) {
        int m0 = bm + wm + mt * 16 + g;           // global row (b*Sq + s)
#pragma unroll
        for (int nt = 0; nt < 4; nt++) {
            int c = bn + wn + nt * 8 + 2 * tq;    // even column
            float bv0 = bias[c], bv1 = bias[c + 1];
            float v0 = acc[mt][nt][0] + bv0;      // row m0,   col c
            float v1 = acc[mt][nt][1] + bv1;      // row m0,   col c+1
            float v2 = acc[mt][nt][2] + bv0;      // row m0+8, col c
            float v3 = acc[mt][nt][3] + bv1;      // row m0+8, col c+1

            if (ROPE) {
                int s0 = m0 & (Sq - 1);
                int s8 = s0 + 8;
                if (c < 1024) {
                    int i = (c >> 1) & 31;
                    float c0 = g_cos[s0 * 32 + i], n0 = g_sin[s0 * 32 + i];
                    float c8 = g_cos[s8 * 32 + i], n8 = g_sin[s8 * 32 + i];
                    uint2 o0, o1;
                    o0.x = f2tf32((v0 * c0 - v1 * n0) * 0.125f);
                    o0.y = f2tf32((v0 * n0 + v1 * c0) * 0.125f);
                    o1.x = f2tf32((v2 * c8 - v3 * n8) * 0.125f);
                    o1.y = f2tf32((v2 * n8 + v3 * c8) * 0.125f);
                    *(uint2*)&g_q[(size_t)m0 * Eq + c]       = o0;
                    *(uint2*)&g_q[(size_t)(m0 + 8) * Eq + c] = o1;
                } else if (c < 1088) {
                    int i = ((c - 1024) >> 1) & 31;
                    float c0 = g_cos[s0 * 32 + i], n0 = g_sin[s0 * 32 + i];
                    float c8 = g_cos[s8 * 32 + i], n8 = g_sin[s8 * 32 + i];
                    uint2 o0, o1;
                    o0.x = f2tf32(v0 * c0 - v1 * n0);
                    o0.y = f2tf32(v0 * n0 + v1 * c0);
                    o1.x = f2tf32(v2 * c8 - v3 * n8);
                    o1.y = f2tf32(v2 * n8 + v3 * c8);
                    *(uint2*)&g_k[(size_t)m0 * 64 + (c - 1024)]       = o0;
                    *(uint2*)&g_k[(size_t)(m0 + 8) * 64 + (c - 1024)] = o1;
                } else {
                    uint2 o0, o1;
                    o0.x = f2tf32(v0); o0.y = f2tf32(v1);
                    o1.x = f2tf32(v2); o1.y = f2tf32(v3);
                    *(uint2*)&g_v[(size_t)m0 * 64 + (c - 1088)]       = o0;
                    *(uint2*)&g_v[(size_t)(m0 + 8) * 64 + (c - 1088)] = o1;
                }
            } else {
                *(float2*)&C[(size_t)m0 * N + c]       = make_float2(v0, v1);
                *(float2*)&C[(size_t)(m0 + 8) * N + c] = make_float2(v2, v3);
            }
        }
    }
}

__global__ __launch_bounds__(256, 2) void gemm_qkv_kernel(const float* __restrict__ x,
                                                          const float* __restrict__ w,
                                                          const float* __restrict__ bias) {
    gemm_body<QKVq, true, true>((const unsigned*)x, (const unsigned*)w, bias, nullptr);
}

__global__ __launch_bounds__(256, 2) void gemm_out_kernel(const float* __restrict__ w,
                                                          const float* __restrict__ bias,
                                                          float* __restrict__ out) {
    gemm_body<Eq, false, false>(g_attn, (const unsigned*)w, bias, out);
}

// ---------------------------------------------------------------------------
// MQA flash attention, tensor-core, cp.async double-buffered.
// Block: 16 seq positions x all 16 heads = 256 mma rows; 512 thr, 16 warps.
// warp w = position qbase + w (16 head-rows). K/V staged ONCE per block for
// all 16 warps. Single barrier per KV tile.
// smem: QP 256x68 (Q then P), Ks 2x64x68, Vs 2x64x72 = 141312 B dynamic.
// ---------------------------------------------------------------------------
__global__ __launch_bounds__(512, 1) void attn_tc_kernel() {
    extern __shared__ unsigned sm[];
    unsigned* QP = sm;                               // 256*68
    unsigned* Ks = sm + 256 * 68;                    // 2*64*68
    unsigned* Vs = sm + 256 * 68 + 2 * 64 * 68;      // 2*64*72

    const int b     = blockIdx.y;
    const int qb    = 127 - (int)blockIdx.x;   // reversed: long blocks first
    const int qbase = qb * 16;
    const int tid   = threadIdx.x;
    const int w     = tid >> 5;
    const int lane  = tid & 31;
    const int g     = lane >> 2;
    const int tq    = lane & 3;

    unsigned smb  = (unsigned)__cvta_generic_to_shared(sm);
    const unsigned qp_b = smb;
    const unsigned ks_b = smb + 256u * 68u * 4u;
    const unsigned vs_b = smb + (256u * 68u + 2u * 64u * 68u) * 4u;

    // Stage Q (group 0): row r = pos_local*16 + head
#pragma unroll
    for (int i = 0; i < 8; i++) {
        int c = tid + i * 512;
        int r = c >> 4, col = (c & 15) * 4;
        const unsigned* src = g_q + (((size_t)(b * Sq + qbase + (r >> 4))) << 10)
                              + ((r & 15) << 6) + col;
        CP16(qp_b + (unsigned)(r * 68 + col) * 4u, src);
    }
    CPC;

    const int n_tiles = (qbase + 79) >> 6;

    // Stage KV tile 0 (group 1)
    {
        const unsigned* kp = g_k + ((size_t)(b * Sq)) * 64;
        const unsigned* vp = g_v + ((size_t)(b * Sq)) * 64;
#pragma unroll
        for (int i = 0; i < 2; i++) {
            int c = tid + i * 512;
            int r = c >> 4, col = (c & 15) * 4;
            CP16(ks_b + (unsigned)(r * 68 + col) * 4u, kp + r * 64 + col);
            CP16(vs_b + (unsigned)(r * 72 + col) * 4u, vp + r * 64 + col);
        }
    }
    CPC;
    CPW(1);            // Q complete (KV0 may still be in flight)
    __syncthreads();

    // Preload Q fragments (warp's private 16 rows); QP rows reused as P after
    const int r0 = w * 16 + g;
    unsigned qa[8][4];
#pragma unroll
    for (int ks = 0; ks < 8; ks++) {
        qa[ks][0] = QP[r0 * 68 + ks * 8 + tq];
        qa[ks][1] = QP[(r0 + 8) * 68 + ks * 8 + tq];
        qa[ks][2] = QP[r0 * 68 + ks * 8 + tq + 4];
        qa[ks][3] = QP[(r0 + 8) * 68 + ks * 8 + tq + 4];
    }

    float o[8][4];
#pragma unroll
    for (int nt = 0; nt < 8; nt++)
#pragma unroll
        for (int e = 0; e < 4; e++) o[nt][e] = 0.f;
    float mr0 = -1e30f, mr1 = -1e30f, l0 = 0.f, l1 = 0.f;
    const int qpos = qbase + w;

    for (int kt = 0; kt < n_tiles; kt++) {
        const int buf = kt & 1;
        CPW(0);
        __syncthreads();

        // Issue next KV tile into the other buffer (safe after barrier)
        if (kt + 1 < n_tiles) {
            const int kb2 = (kt + 1) * 64;
            const unsigned* kp = g_k + ((size_t)(b * Sq + kb2)) * 64;
            const unsigned* vp = g_v + ((size_t)(b * Sq + kb2)) * 64;
            unsigned kd = ks_b + (unsigned)((buf ^ 1) * 4352) * 4u;
            unsigned vd = vs_b + (unsigned)((buf ^ 1) * 4608) * 4u;
#pragma unroll
            for (int i = 0; i < 2; i++) {
                int c = tid + i * 512;
                int r = c >> 4, col = (c & 15) * 4;
                CP16(kd + (unsigned)(r * 68 + col) * 4u, kp + r * 64 + col);
                CP16(vd + (unsigned)(r * 72 + col) * 4u, vp + r * 64 + col);
            }
            CPC;
        }

        const unsigned* Kc = Ks + buf * 4352;
        const unsigned* Vc = Vs + buf * 4608;
        const int kb = kt * 64;

        // S = Q K^T  (16 rows x 64 keys per warp)
        float sc[8][4];
#pragma unroll
        for (int nt = 0; nt < 8; nt++)
#pragma unroll
            for (int e = 0; e < 4; e++) sc[nt][e] = 0.f;
#pragma unroll
        for (int ks = 0; ks < 8; ks++) {
#pragma unroll
            for (int nt = 0; nt < 8; nt++) {
                unsigned b0 = Kc[(nt * 8 + g) * 68 + ks * 8 + tq];
                unsigned b1 = Kc[(nt * 8 + g) * 68 + ks * 8 + tq + 4];
                mma_tf32(sc[nt], qa[ks], b0, b1);
            }
        }

        // Causal mask (same qpos for both row-halves of this warp)
        if (kb + 63 > qpos) {
#pragma unroll
            for (int nt = 0; nt < 8; nt++) {
                int key = kb + nt * 8 + 2 * tq;
                if (key > qpos)     { sc[nt][0] = -1e30f; sc[nt][2] = -1e30f; }
                if (key + 1 > qpos) { sc[nt][1] = -1e30f; sc[nt][3] = -1e30f; }
            }
        }

        // Online softmax (rows = heads g and g+8; reduce over quad lanes)
        float mx0 = -1e30f, mx1 = -1e30f;
#pragma unroll
        for (int nt = 0; nt < 8; nt++) {
            mx0 = fmaxf(mx0, fmaxf(sc[nt][0], sc[nt][1]));
            mx1 = fmaxf(mx1, fmaxf(sc[nt][2], sc[nt][3]));
        }
        mx0 = fmaxf(mx0, __shfl_xor_sync(0xFFFFFFFFu, mx0, 1));
        mx0 = fmaxf(mx0, __shfl_xor_sync(0xFFFFFFFFu, mx0, 2));
        mx1 = fmaxf(mx1, __shfl_xor_sync(0xFFFFFFFFu, mx1, 1));
        mx1 = fmaxf(mx1, __shfl_xor_sync(0xFFFFFFFFu, mx1, 2));

        float mn0 = fmaxf(mr0, mx0);
        float mn1 = fmaxf(mr1, mx1);
        float corr0 = __expf(mr0 - mn0);
        float corr1 = __expf(mr1 - mn1);
        float sum0 = 0.f, sum1 = 0.f;
#pragma unroll
        for (int nt = 0; nt < 8; nt++) {
            sc[nt][0] = __expf(sc[nt][0] - mn0);
            sc[nt][1] = __expf(sc[nt][1] - mn0);
            sc[nt][2] = __expf(sc[nt][2] - mn1);
            sc[nt][3] = __expf(sc[nt][3] - mn1);
            sum0 += sc[nt][0] + sc[nt][1];
            sum1 += sc[nt][2] + sc[nt][3];
        }
        sum0 += __shfl_xor_sync(0xFFFFFFFFu, sum0, 1);
        sum0 += __shfl_xor_sync(0xFFFFFFFFu, sum0, 2);
        sum1 += __shfl_xor_sync(0xFFFFFFFFu, sum1, 1);
        sum1 += __shfl_xor_sync(0xFFFFFFFFu, sum1, 2);

        mr0 = mn0; mr1 = mn1;
        l0 = l0 * corr0 + sum0;
        l1 = l1 * corr1 + sum1;
#pragma unroll
        for (int nt = 0; nt < 8; nt++) {
            o[nt][0] *= corr0; o[nt][1] *= corr0;
            o[nt][2] *= corr1; o[nt][3] *= corr1;
        }

        // Store P (tf32) into this warp's private QP rows
#pragma unroll
        for (int nt = 0; nt < 8; nt++) {
            uint2 p0, p1;
            p0.x = f2tf32(sc[nt][0]); p0.y = f2tf32(sc[nt][1]);
            p1.x = f2tf32(sc[nt][2]); p1.y = f2tf32(sc[nt][3]);
            *(uint2*)&QP[r0 * 68 + nt * 8 + 2 * tq]       = p0;
            *(uint2*)&QP[(r0 + 8) * 68 + nt * 8 + 2 * tq] = p1;
        }
        __syncwarp();

        // O += P V
#pragma unroll
        for (int ks = 0; ks < 8; ks++) {
            unsigned pa[4];
            pa[0] = QP[r0 * 68 + ks * 8 + tq];
            pa[1] = QP[(r0 + 8) * 68 + ks * 8 + tq];
            pa[2] = QP[r0 * 68 + ks * 8 + tq + 4];
            pa[3] = QP[(r0 + 8) * 68 + ks * 8 + tq + 4];
#pragma unroll
            for (int nt = 0; nt < 8; nt++) {
                unsigned b0 = Vc[(ks * 8 + tq) * 72 + nt * 8 + g];
                unsigned b1 = Vc[(ks * 8 + tq + 4) * 72 + nt * 8 + g];
                mma_tf32(o[nt], pa, b0, b1);
            }
        }
    }

    // Epilogue: normalize, write tf32 to g_attn[b][qpos][head*64+d]
    float inv0 = 1.f / l0;
    float inv1 = 1.f / l1;
    unsigned* dst0 = g_attn + (((size_t)(b * Sq + qpos)) << 10) + (g << 6);
    unsigned* dst1 = g_attn + (((size_t)(b * Sq + qpos)) << 10) + ((g + 8) << 6);
#pragma unroll
    for (int nt = 0; nt < 8; nt++) {
        int c = nt * 8 + 2 * tq;
        uint2 a0, a1;
        a0.x = f2tf32(o[nt][0] * inv0); a0.y = f2tf32(o[nt][1] * inv0);
        a1.x = f2tf32(o[nt][2] * inv1); a1.y = f2tf32(o[nt][3] * inv1);
        *(uint2*)&dst0[c] = a0;
        *(uint2*)&dst1[c] = a1;
    }
}

// ---------------------------------------------------------------------------
extern "C" void kernel_launch(void* const* d_in, const int* in_sizes, int n_in,
                              void* d_out, int out_size) {
    const float* x     = (const float*)d_in[0];
    const float* qkv_w = (const float*)d_in[1];
    const float* qkv_b = (const float*)d_in[2];
    const float* out_w = (const float*)d_in[3];
    const float* out_b = (const float*)d_in[4];
    float* out = (float*)d_out;

    const int GEMM_SMEM = 2 * 128 * 36 * 2 * 4;                        // 73728
    const int ATTN_SMEM = (256 * 68 + 2 * 64 * 68 + 2 * 64 * 72) * 4;  // 141312

    cudaFuncSetAttribute(gemm_qkv_kernel, cudaFuncAttributeMaxDynamicSharedMemorySize, GEMM_SMEM);
    cudaFuncSetAttribute(gemm_out_kernel, cudaFuncAttributeMaxDynamicSharedMemorySize, GEMM_SMEM);
    cudaFuncSetAttribute(attn_tc_kernel,  cudaFuncAttributeMaxDynamicSharedMemorySize, ATTN_SMEM);

    // 1. RoPE tables (must precede QKV GEMM epilogue)
    rope_tables_kernel<<<(Sq * 32 + 255) / 256, 256>>>();

    // 2. QKV projection + bias + RoPE + scale + tf32 pack (fused epilogue)
    gemm_qkv_kernel<<<dim3(QKVq / 128, (Bq * Sq) / 128), 256, GEMM_SMEM>>>(x, qkv_w, qkv_b);

    // 3. Causal MQA flash attention -> g_attn (tf32)
    attn_tc_kernel<<<dim3(Sq / 16, Bq), 512, ATTN_SMEM>>>();

    // 4. Output projection + bias -> out (fp32)
    gemm_out_kernel<<<dim3(Eq / 128, (Bq * Sq) / 128), 256, GEMM_SMEM>>>(out_w, out_b, out);
}

// round 7
// speedup vs baseline: 1.0300x; 1.0300x over previous
#include <cuda_runtime.h>
#include <math.h>
#include <cstdint>

// Problem constants
#define Bq   2
#define Sq   2048
#define Eq   1024
#define Hq   16
#define QKVq 1152    // (16 + 2*1) * 64

// Scratch (device globals — no runtime allocation allowed)
__device__ unsigned g_q[(size_t)Bq * Sq * Eq];       // tf32, roped, scaled
__device__ unsigned g_k[(size_t)Bq * Sq * 64];       // tf32, roped
__device__ unsigned g_v[(size_t)Bq * Sq * 64];       // tf32
__device__ unsigned g_attn[(size_t)Bq * Sq * Eq];    // attention out (tf32)
__device__ float    g_cos[Sq * 32];
__device__ float    g_sin[Sq * 32];

// ---------------------------------------------------------------------------
__device__ __forceinline__ unsigned f2tf32(float x) {
    unsigned r;
    asm("cvt.rna.tf32.f32 %0, %1;" : "=r"(r) : "f"(x));
    return r;
}

// Round raw fp32 bits to nearest at the tf32 cutoff (bit 13).
__device__ __forceinline__ unsigned rnd13(unsigned u) { return u + 0x1000u; }

__device__ __forceinline__ void mma_tf32(float* d, const unsigned* a,
                                         unsigned b0, unsigned b1) {
    asm volatile(
        "mma.sync.aligned.m16n8k8.row.col.f32.tf32.tf32.f32 "
        "{%0,%1,%2,%3}, {%4,%5,%6,%7}, {%8,%9}, {%0,%1,%2,%3};\n"
        : "+f"(d[0]), "+f"(d[1]), "+f"(d[2]), "+f"(d[3])
        : "r"(a[0]), "r"(a[1]), "r"(a[2]), "r"(a[3]), "r"(b0), "r"(b1));
}

// ldmatrix x4: 4 8x8-b16 tiles; per-lane shared address in r-addr
__device__ __forceinline__ void ldsm4(unsigned* r, uint32_t addr) {
    asm volatile("ldmatrix.sync.aligned.m8n8.x4.shared.b16 {%0,%1,%2,%3}, [%4];"
                 : "=r"(r[0]), "=r"(r[1]), "=r"(r[2]), "=r"(r[3]) : "r"(addr));
}

#define CP16(dst, src) asm volatile("cp.async.cg.shared.global [%0], [%1], 16;\n" :: "r"(dst), "l"(src))
#define CPC            asm volatile("cp.async.commit_group;\n")
#define CPW(n)         asm volatile("cp.async.wait_group %0;\n" :: "n"(n))

__device__ __forceinline__ uint32_t smem_u32(const void* p) {
    uint32_t a;
    asm("{ .reg .u64 t; cvta.to.shared.u64 t, %1; cvt.u32.u64 %0, t; }" : "=r"(a) : "l"(p));
    return a;
}

// ---------------------------------------------------------------------------
// RoPE tables
// ---------------------------------------------------------------------------
__global__ void rope_tables_kernel() {
    int idx = blockIdx.x * blockDim.x + threadIdx.x;
    if (idx >= Sq * 32) return;
    int s = idx >> 5;
    int i = idx & 31;
    double inv = exp(-(2.0 * i / 64.0) * log(10000.0));
    double ang = (double)s * inv;
    g_cos[idx] = (float)cos(ang);
    g_sin[idx] = (float)sin(ang);
}

// ---------------------------------------------------------------------------
// Double-buffered tf32 tensor GEMM (NT): C = A * W^T + bias
// Block 128x128, BK=32, 256 thr (8 warps: 2m x 4n), warp tile 64x32.
// Fragments loaded via ldmatrix.x4 (1 LDSM per m16k8 A-frag; 1 per 2 B-frags).
// RND_A/RND_B: round raw fp32 fragments to tf32-nearest after LDSM.
// ROPE epilogue: bias + RoPE + 0.125 scale -> tf32 g_q/g_k/g_v.
// ---------------------------------------------------------------------------
template <int N, bool ROPE, bool RND_A>
__device__ __forceinline__ void gemm_body(const unsigned* __restrict__ A,
                                          const unsigned* __restrict__ W,
                                          const float* __restrict__ bias,
                                          float* __restrict__ C) {
    extern __shared__ unsigned sm[];

    const int tid  = threadIdx.x;
    const int warp = tid >> 5;
    const int lane = tid & 31;
    const int g    = lane >> 2;
    const int tq   = lane & 3;
    const int sub  = lane >> 3;        // ldmatrix tile index 0..3
    const int wm   = (warp & 1) * 64;
    const int wn   = (warp >> 1) * 32;
    const int bm   = blockIdx.y * 128;
    const int bn   = blockIdx.x * 128;

    const uint32_t sA0 = smem_u32(sm);                 // [2][128][36] words
    const uint32_t sB0 = sA0 + 2u * 128u * 36u * 4u;   // [2][128][36] words

    // Per-lane ldmatrix addresses (buffer 0).
    // A-frag (m16k8): tiles [r0..7 w0-3][r8..15 w0-3][r0..7 w4-7][r8..15 w4-7]
    uint32_t aaddr[4];
#pragma unroll
    for (int mt = 0; mt < 4; mt++) {
        int row  = wm + mt * 16 + (sub & 1) * 8 + (lane & 7);
        int word = (sub >> 1) * 4;
        aaddr[mt] = sA0 + (uint32_t)(row * 36 + word) * 4u;
    }
    // B pair p covers nt = 2p, 2p+1: tiles [nt0 w0][nt0 w4][nt1 w0][nt1 w4]
    uint32_t baddr[2];
#pragma unroll
    for (int p = 0; p < 2; p++) {
        int nt   = p * 2 + (sub >> 1);
        int word = (sub & 1) * 4;
        int row  = wn + nt * 8 + (lane & 7);
        baddr[p] = sB0 + (uint32_t)(row * 36 + word) * 4u;
    }

    float acc[4][4][4];
#pragma unroll
    for (int mt = 0; mt < 4; mt++)
#pragma unroll
        for (int nt = 0; nt < 4; nt++)
#pragma unroll
            for (int e = 0; e < 4; e++) acc[mt][nt][e] = 0.f;

    // prologue: stage buf 0
#pragma unroll
    for (int i = 0; i < 4; i++) {
        int c = tid + i * 256;
        int r = c >> 3, col = (c & 7) * 4;
        CP16(sA0 + (uint32_t)(r * 36 + col) * 4u, A + (size_t)(bm + r) * Eq + col);
        CP16(sB0 + (uint32_t)(r * 36 + col) * 4u, W + (size_t)(bn + r) * Eq + col);
    }
    CPC;

    for (int k0 = 0; k0 < Eq; k0 += 32) {
        const int buf = (k0 >> 5) & 1;
        const uint32_t bo = (uint32_t)buf * 18432u;    // 4608 words
        CPW(0);
        __syncthreads();

        if (k0 + 32 < Eq) {
            uint32_t da = sA0 + ((uint32_t)(buf ^ 1)) * 18432u;
            uint32_t db = sB0 + ((uint32_t)(buf ^ 1)) * 18432u;
#pragma unroll
            for (int i = 0; i < 4; i++) {
                int c = tid + i * 256;
                int r = c >> 3, col = (c & 7) * 4;
                CP16(da + (uint32_t)(r * 36 + col) * 4u, A + (size_t)(bm + r) * Eq + k0 + 32 + col);
                CP16(db + (uint32_t)(r * 36 + col) * 4u, W + (size_t)(bn + r) * Eq + k0 + 32 + col);
            }
            CPC;
        }

#pragma unroll
        for (int ks = 0; ks < 4; ks++) {
            const uint32_t kso = bo + (uint32_t)ks * 32u;
            unsigned a[4][4];
#pragma unroll
            for (int mt = 0; mt < 4; mt++) {
                ldsm4(a[mt], aaddr[mt] + kso);
                if (RND_A) {
                    a[mt][0] = rnd13(a[mt][0]); a[mt][1] = rnd13(a[mt][1]);
                    a[mt][2] = rnd13(a[mt][2]); a[mt][3] = rnd13(a[mt][3]);
                }
            }
            unsigned bf[2][4];
#pragma unroll
            for (int p = 0; p < 2; p++) {
                ldsm4(bf[p], baddr[p] + kso);
                bf[p][0] = rnd13(bf[p][0]); bf[p][1] = rnd13(bf[p][1]);
                bf[p][2] = rnd13(bf[p][2]); bf[p][3] = rnd13(bf[p][3]);
            }
#pragma unroll
            for (int nt = 0; nt < 4; nt++) {
                unsigned b0 = bf[nt >> 1][(nt & 1) * 2];
                unsigned b1 = bf[nt >> 1][(nt & 1) * 2 + 1];
#pragma unroll
                for (int mt = 0; mt < 4; mt++)
                    mma_tf32(acc[mt][nt], a[mt], b0, b1);
            }
        }
    }

    // Epilogue
#pragma unroll
    for (int mt = 0; mt < 4; mt++) {
        int m0 = bm + wm + mt * 16 + g;
#pragma unroll
        for (int nt = 0; nt < 4; nt++) {
            int c = bn + wn + nt * 8 + 2 * tq;
            float bv0 = bias[c], bv1 = bias[c + 1];
            float v0 = acc[mt][nt][0] + bv0;
            float v1 = acc[mt][nt][1] + bv1;
            float v2 = acc[mt][nt][2] + bv0;
            float v3 = acc[mt][nt][3] + bv1;

            if (ROPE) {
                int s0 = m0 & (Sq - 1);
                int s8 = s0 + 8;
                if (c < 1024) {
                    int i = (c >> 1) & 31;
                    float c0 = g_cos[s0 * 32 + i], n0 = g_sin[s0 * 32 + i];
                    float c8 = g_cos[s8 * 32 + i], n8 = g_sin[s8 * 32 + i];
                    uint2 o0, o1;
                    o0.x = f2tf32((v0 * c0 - v1 * n0) * 0.125f);
                    o0.y = f2tf32((v0 * n0 + v1 * c0) * 0.125f);
                    o1.x = f2tf32((v2 * c8 - v3 * n8) * 0.125f);
                    o1.y = f2tf32((v2 * n8 + v3 * c8) * 0.125f);
                    *(uint2*)&g_q[(size_t)m0 * Eq + c]       = o0;
                    *(uint2*)&g_q[(size_t)(m0 + 8) * Eq + c] = o1;
                } else if (c < 1088) {
                    int i = ((c - 1024) >> 1) & 31;
                    float c0 = g_cos[s0 * 32 + i], n0 = g_sin[s0 * 32 + i];
                    float c8 = g_cos[s8 * 32 + i], n8 = g_sin[s8 * 32 + i];
                    uint2 o0, o1;
                    o0.x = f2tf32(v0 * c0 - v1 * n0);
                    o0.y = f2tf32(v0 * n0 + v1 * c0);
                    o1.x = f2tf32(v2 * c8 - v3 * n8);
                    o1.y = f2tf32(v2 * n8 + v3 * c8);
                    *(uint2*)&g_k[(size_t)m0 * 64 + (c - 1024)]       = o0;
                    *(uint2*)&g_k[(size_t)(m0 + 8) * 64 + (c - 1024)] = o1;
                } else {
                    uint2 o0, o1;
                    o0.x = f2tf32(v0); o0.y = f2tf32(v1);
                    o1.x = f2tf32(v2); o1.y = f2tf32(v3);
                    *(uint2*)&g_v[(size_t)m0 * 64 + (c - 1088)]       = o0;
                    *(uint2*)&g_v[(size_t)(m0 + 8) * 64 + (c - 1088)] = o1;
                }
            } else {
                *(float2*)&C[(size_t)m0 * N + c]       = make_float2(v0, v1);
                *(float2*)&C[(size_t)(m0 + 8) * N + c] = make_float2(v2, v3);
            }
        }
    }
}

__global__ __launch_bounds__(256, 2) void gemm_qkv_kernel(const float* __restrict__ x,
                                                          const float* __restrict__ w,
                                                          const float* __restrict__ bias) {
    gemm_body<QKVq, true, true>((const unsigned*)x, (const unsigned*)w, bias, nullptr);
}

__global__ __launch_bounds__(256, 2) void gemm_out_kernel(const float* __restrict__ w,
                                                          const float* __restrict__ bias,
                                                          float* __restrict__ out) {
    gemm_body<Eq, false, false>(g_attn, (const unsigned*)w, bias, out);
}

// ---------------------------------------------------------------------------
// MQA flash attention, cp.async double-buffered, ldmatrix fragments.
// Block: 16 seq positions x 16 heads = 256 mma rows; 512 thr, 16 warps.
// ---------------------------------------------------------------------------
__global__ __launch_bounds__(512, 1) void attn_tc_kernel() {
    extern __shared__ unsigned sm[];
    unsigned* QP = sm;                               // 256*68 (Q, then P as fp32)
    unsigned* Vs = sm + 256 * 68 + 2 * 64 * 68;      // 2*64*72

    const int b     = blockIdx.y;
    const int qb    = 127 - (int)blockIdx.x;
    const int qbase = qb * 16;
    const int tid   = threadIdx.x;
    const int w     = tid >> 5;
    const int lane  = tid & 31;
    const int g     = lane >> 2;
    const int tq    = lane & 3;
    const int sub   = lane >> 3;

    const uint32_t smb  = smem_u32(sm);
    const uint32_t qp_b = smb;
    const uint32_t ks_b = smb + 256u * 68u * 4u;
    const uint32_t vs_b = smb + (256u * 68u + 2u * 64u * 68u) * 4u;

    // Per-lane ldmatrix addresses
    // A-frag rows in QP (Q now, P later): same tile layout both times
    const uint32_t qaddr = qp_b +
        (uint32_t)((w * 16 + (sub & 1) * 8 + (lane & 7)) * 68 + (sub >> 1) * 4) * 4u;
    // K-frags: 4 pairs cover nt 0..7
    uint32_t kaddr[4];
#pragma unroll
    for (int p = 0; p < 4; p++) {
        int nt   = p * 2 + (sub >> 1);
        int word = (sub & 1) * 4;
        int row  = nt * 8 + (lane & 7);
        kaddr[p] = ks_b + (uint32_t)(row * 68 + word) * 4u;
    }

    // Stage Q: row r = pos_local*16 + head
#pragma unroll
    for (int i = 0; i < 8; i++) {
        int c = tid + i * 512;
        int r = c >> 4, col = (c & 15) * 4;
        const unsigned* src = g_q + (((size_t)(b * Sq + qbase + (r >> 4))) << 10)
                              + ((r & 15) << 6) + col;
        CP16(qp_b + (uint32_t)(r * 68 + col) * 4u, src);
    }
    CPC;

    const int n_tiles = (qbase + 79) >> 6;

    // Stage KV tile 0
    {
        const unsigned* kp = g_k + ((size_t)(b * Sq)) * 64;
        const unsigned* vp = g_v + ((size_t)(b * Sq)) * 64;
#pragma unroll
        for (int i = 0; i < 2; i++) {
            int c = tid + i * 512;
            int r = c >> 4, col = (c & 15) * 4;
            CP16(ks_b + (uint32_t)(r * 68 + col) * 4u, kp + r * 64 + col);
            CP16(vs_b + (uint32_t)(r * 72 + col) * 4u, vp + r * 64 + col);
        }
    }
    CPC;
    CPW(1);
    __syncthreads();

    // Preload Q fragments via ldmatrix; QP rows reused as P after
    unsigned qa[8][4];
#pragma unroll
    for (int ks = 0; ks < 8; ks++) ldsm4(qa[ks], qaddr + (uint32_t)ks * 32u);

    float o[8][4];
#pragma unroll
    for (int nt = 0; nt < 8; nt++)
#pragma unroll
        for (int e = 0; e < 4; e++) o[nt][e] = 0.f;
    float mr0 = -1e30f, mr1 = -1e30f, l0 = 0.f, l1 = 0.f;
    const int qpos  = qbase + w;
    const int r0    = w * 16 + g;

    for (int kt = 0; kt < n_tiles; kt++) {
        const int buf = kt & 1;
        CPW(0);
        __syncthreads();

        if (kt + 1 < n_tiles) {
            const int kb2 = (kt + 1) * 64;
            const unsigned* kp = g_k + ((size_t)(b * Sq + kb2)) * 64;
            const unsigned* vp = g_v + ((size_t)(b * Sq + kb2)) * 64;
            uint32_t kd = ks_b + (uint32_t)((buf ^ 1) * 4352) * 4u;
            uint32_t vd = vs_b + (uint32_t)((buf ^ 1) * 4608) * 4u;
#pragma unroll
            for (int i = 0; i < 2; i++) {
                int c = tid + i * 512;
                int r = c >> 4, col = (c & 15) * 4;
                CP16(kd + (uint32_t)(r * 68 + col) * 4u, kp + r * 64 + col);
                CP16(vd + (uint32_t)(r * 72 + col) * 4u, vp + r * 64 + col);
            }
            CPC;
        }

        const uint32_t kbo = (uint32_t)(buf * 4352) * 4u;
        const unsigned* Vc = Vs + buf * 4608;
        const int kb = kt * 64;

        // S = Q K^T  (16 rows x 64 keys per warp)
        float sc[8][4];
#pragma unroll
        for (int nt = 0; nt < 8; nt++)
#pragma unroll
            for (int e = 0; e < 4; e++) sc[nt][e] = 0.f;
#pragma unroll
        for (int ks = 0; ks < 8; ks++) {
            unsigned kf[4][4];
#pragma unroll
            for (int p = 0; p < 4; p++) ldsm4(kf[p], kaddr[p] + kbo + (uint32_t)ks * 32u);
#pragma unroll
            for (int nt = 0; nt < 8; nt++) {
                unsigned b0 = kf[nt >> 1][(nt & 1) * 2];
                unsigned b1 = kf[nt >> 1][(nt & 1) * 2 + 1];
                mma_tf32(sc[nt], qa[ks], b0, b1);
            }
        }

        // Causal mask
        if (kb + 63 > qpos) {
#pragma unroll
            for (int nt = 0; nt < 8; nt++) {
                int key = kb + nt * 8 + 2 * tq;
                if (key > qpos)     { sc[nt][0] = -1e30f; sc[nt][2] = -1e30f; }
                if (key + 1 > qpos) { sc[nt][1] = -1e30f; sc[nt][3] = -1e30f; }
            }
        }

        // Online softmax
        float mx0 = -1e30f, mx1 = -1e30f;
#pragma unroll
        for (int nt = 0; nt < 8; nt++) {
            mx0 = fmaxf(mx0, fmaxf(sc[nt][0], sc[nt][1]));
            mx1 = fmaxf(mx1, fmaxf(sc[nt][2], sc[nt][3]));
        }
        mx0 = fmaxf(mx0, __shfl_xor_sync(0xFFFFFFFFu, mx0, 1));
        mx0 = fmaxf(mx0, __shfl_xor_sync(0xFFFFFFFFu, mx0, 2));
        mx1 = fmaxf(mx1, __shfl_xor_sync(0xFFFFFFFFu, mx1, 1));
        mx1 = fmaxf(mx1, __shfl_xor_sync(0xFFFFFFFFu, mx1, 2));

        float mn0 = fmaxf(mr0, mx0);
        float mn1 = fmaxf(mr1, mx1);
        float corr0 = __expf(mr0 - mn0);
        float corr1 = __expf(mr1 - mn1);
        float sum0 = 0.f, sum1 = 0.f;
#pragma unroll
        for (int nt = 0; nt < 8; nt++) {
            sc[nt][0] = __expf(sc[nt][0] - mn0);
            sc[nt][1] = __expf(sc[nt][1] - mn0);
            sc[nt][2] = __expf(sc[nt][2] - mn1);
            sc[nt][3] = __expf(sc[nt][3] - mn1);
            sum0 += sc[nt][0] + sc[nt][1];
            sum1 += sc[nt][2] + sc[nt][3];
        }
        sum0 += __shfl_xor_sync(0xFFFFFFFFu, sum0, 1);
        sum0 += __shfl_xor_sync(0xFFFFFFFFu, sum0, 2);
        sum1 += __shfl_xor_sync(0xFFFFFFFFu, sum1, 1);
        sum1 += __shfl_xor_sync(0xFFFFFFFFu, sum1, 2);

        mr0 = mn0; mr1 = mn1;
        l0 = l0 * corr0 + sum0;
        l1 = l1 * corr1 + sum1;
#pragma unroll
        for (int nt = 0; nt < 8; nt++) {
            o[nt][0] *= corr0; o[nt][1] *= corr0;
            o[nt][2] *= corr1; o[nt][3] *= corr1;
        }

        // Store P (raw fp32; rounded to tf32-nearest at fragment load)
        float* QPf = (float*)QP;
#pragma unroll
        for (int nt = 0; nt < 8; nt++) {
            *(float2*)&QPf[r0 * 68 + nt * 8 + 2 * tq]       = make_float2(sc[nt][0], sc[nt][1]);
            *(float2*)&QPf[(r0 + 8) * 68 + nt * 8 + 2 * tq] = make_float2(sc[nt][2], sc[nt][3]);
        }
        __syncwarp();

        // O += P V
#pragma unroll
        for (int ks = 0; ks < 8; ks++) {
            unsigned pa[4];
            ldsm4(pa, qaddr + (uint32_t)ks * 32u);
            pa[0] = rnd13(pa[0]); pa[1] = rnd13(pa[1]);
            pa[2] = rnd13(pa[2]); pa[3] = rnd13(pa[3]);
#pragma unroll
            for (int nt = 0; nt < 8; nt++) {
                unsigned b0 = Vc[(ks * 8 + tq) * 72 + nt * 8 + g];
                unsigned b1 = Vc[(ks * 8 + tq + 4) * 72 + nt * 8 + g];
                mma_tf32(o[nt], pa, b0, b1);
            }
        }
    }

    // Epilogue: normalize, write tf32 to g_attn[b][qpos][head*64+d]
    float inv0 = 1.f / l0;
    float inv1 = 1.f / l1;
    unsigned* dst0 = g_attn + (((size_t)(b * Sq + qpos)) << 10) + (g << 6);
    unsigned* dst1 = g_attn + (((size_t)(b * Sq + qpos)) << 10) + ((g + 8) << 6);
#pragma unroll
    for (int nt = 0; nt < 8; nt++) {
        int c = nt * 8 + 2 * tq;
        uint2 a0, a1;
        a0.x = f2tf32(o[nt][0] * inv0); a0.y = f2tf32(o[nt][1] * inv0);
        a1.x = f2tf32(o[nt][2] * inv1); a1.y = f2tf32(o[nt][3] * inv1);
        *(uint2*)&dst0[c] = a0;
        *(uint2*)&dst1[c] = a1;
    }
}

// ---------------------------------------------------------------------------
extern "C" void kernel_launch(void* const* d_in, const int* in_sizes, int n_in,
                              void* d_out, int out_size) {
    const float* x     = (const float*)d_in[0];
    const float* qkv_w = (const float*)d_in[1];
    const float* qkv_b = (const float*)d_in[2];
    const float* out_w = (const float*)d_in[3];
    const float* out_b = (const float*)d_in[4];
    float* out = (float*)d_out;

    const int GEMM_SMEM = 2 * 128 * 36 * 2 * 4;                        // 73728
    const int ATTN_SMEM = (256 * 68 + 2 * 64 * 68 + 2 * 64 * 72) * 4;  // 141312

    cudaFuncSetAttribute(gemm_qkv_kernel, cudaFuncAttributeMaxDynamicSharedMemorySize, GEMM_SMEM);
    cudaFuncSetAttribute(gemm_out_kernel, cudaFuncAttributeMaxDynamicSharedMemorySize, GEMM_SMEM);
    cudaFuncSetAttribute(attn_tc_kernel,  cudaFuncAttributeMaxDynamicSharedMemorySize, ATTN_SMEM);

    // 1. RoPE tables (must precede QKV GEMM epilogue)
    rope_tables_kernel<<<(Sq * 32 + 255) / 256, 256>>>();

    // 2. QKV projection + bias + RoPE + scale + tf32 pack (fused epilogue)
    gemm_qkv_kernel<<<dim3(QKVq / 128, (Bq * Sq) / 128), 256, GEMM_SMEM>>>(x, qkv_w, qkv_b);

    // 3. Causal MQA flash attention -> g_attn (tf32)
    attn_tc_kernel<<<dim3(Sq / 16, Bq), 512, ATTN_SMEM>>>();

    // 4. Output projection + bias -> out (fp32)
    gemm_out_kernel<<<dim3(Eq / 128, (Bq * Sq) / 128), 256, GEMM_SMEM>>>(out_w, out_b, out);
}

// round 8
// speedup vs baseline: 1.0965x; 1.0646x over previous
#include <cuda_runtime.h>
#include <math.h>
#include <cstdint>

// Problem constants
#define Bq   2
#define Sq   2048
#define Eq   1024
#define Hq   16
#define QKVq 1152    // (16 + 2*1) * 64

// Scratch (device globals — no runtime allocation allowed)
__device__ unsigned g_q[(size_t)Bq * Sq * Eq];       // tf32, roped, scaled
__device__ unsigned g_k[(size_t)Bq * Sq * 64];       // tf32, roped   [s][d]
__device__ unsigned g_vT[(size_t)Bq * 64 * Sq];      // tf32, V transposed [d][s]
__device__ unsigned g_attn[(size_t)Bq * Sq * Eq];    // attention out (tf32)
__device__ float    g_cos[Sq * 32];
__device__ float    g_sin[Sq * 32];

// ---------------------------------------------------------------------------
__device__ __forceinline__ unsigned f2tf32(float x) {
    unsigned r;
    asm("cvt.rna.tf32.f32 %0, %1;" : "=r"(r) : "f"(x));
    return r;
}

// Round raw fp32 bits to nearest at the tf32 cutoff (bit 13).
__device__ __forceinline__ unsigned rnd13(unsigned u) { return u + 0x1000u; }

__device__ __forceinline__ void mma_tf32(float* d, const unsigned* a,
                                         unsigned b0, unsigned b1) {
    asm volatile(
        "mma.sync.aligned.m16n8k8.row.col.f32.tf32.tf32.f32 "
        "{%0,%1,%2,%3}, {%4,%5,%6,%7}, {%8,%9}, {%0,%1,%2,%3};\n"
        : "+f"(d[0]), "+f"(d[1]), "+f"(d[2]), "+f"(d[3])
        : "r"(a[0]), "r"(a[1]), "r"(a[2]), "r"(a[3]), "r"(b0), "r"(b1));
}

__device__ __forceinline__ void ldsm4(unsigned* r, uint32_t addr) {
    asm volatile("ldmatrix.sync.aligned.m8n8.x4.shared.b16 {%0,%1,%2,%3}, [%4];"
                 : "=r"(r[0]), "=r"(r[1]), "=r"(r[2]), "=r"(r[3]) : "r"(addr));
}

#define CP16(dst, src) asm volatile("cp.async.cg.shared.global [%0], [%1], 16;\n" :: "r"(dst), "l"(src))
#define CPC            asm volatile("cp.async.commit_group;\n")
#define CPW(n)         asm volatile("cp.async.wait_group %0;\n" :: "n"(n))

__device__ __forceinline__ uint32_t smem_u32(const void* p) {
    uint32_t a;
    asm("{ .reg .u64 t; cvta.to.shared.u64 t, %1; cvt.u32.u64 %0, t; }" : "=r"(a) : "l"(p));
    return a;
}

// ---------------------------------------------------------------------------
// RoPE tables
// ---------------------------------------------------------------------------
__global__ void rope_tables_kernel() {
    int idx = blockIdx.x * blockDim.x + threadIdx.x;
    if (idx >= Sq * 32) return;
    int s = idx >> 5;
    int i = idx & 31;
    double inv = exp(-(2.0 * i / 64.0) * log(10000.0));
    double ang = (double)s * inv;
    g_cos[idx] = (float)cos(ang);
    g_sin[idx] = (float)sin(ang);
}

// ---------------------------------------------------------------------------
// 3-stage cp.async tf32 GEMM (NT): C = A * W^T + bias
// Block tile 256(M) x 128(N), BK=32, 512 thr (16 warps: 4m x 4n),
// warp tile 64x32. ldmatrix fragments, prefetch distance 2 (wait_group 1).
// smem: 3 stages x (A 256x36 + B 128x36) words = 165888 B.
// ROPE epilogue: bias + RoPE + 0.125 scale -> tf32 g_q/g_k/g_vT.
// ---------------------------------------------------------------------------
#define STAGE_B 55296u   // bytes per stage
#define BOFF_B  36864u   // B offset within stage (256*36*4)

template <int N, bool ROPE, bool RND_A>
__device__ __forceinline__ void gemm_body(const unsigned* __restrict__ A,
                                          const unsigned* __restrict__ W,
                                          const float* __restrict__ bias,
                                          float* __restrict__ C) {
    extern __shared__ unsigned sm[];

    const int tid  = threadIdx.x;
    const int warp = tid >> 5;
    const int lane = tid & 31;
    const int g    = lane >> 2;
    const int tq   = lane & 3;
    const int sub  = lane >> 3;
    const int wm   = (warp & 3) * 64;
    const int wn   = (warp >> 2) * 32;
    const int bm   = blockIdx.y * 256;
    const int bn   = blockIdx.x * 128;

    const uint32_t base = smem_u32(sm);

    // Per-lane ldmatrix addresses (stage 0)
    uint32_t aaddr[4];
#pragma unroll
    for (int mt = 0; mt < 4; mt++) {
        int row  = wm + mt * 16 + (sub & 1) * 8 + (lane & 7);
        int word = (sub >> 1) * 4;
        aaddr[mt] = base + (uint32_t)(row * 36 + word) * 4u;
    }
    uint32_t baddr[2];
#pragma unroll
    for (int p = 0; p < 2; p++) {
        int nt   = p * 2 + (sub >> 1);
        int word = (sub & 1) * 4;
        int row  = wn + nt * 8 + (lane & 7);
        baddr[p] = base + BOFF_B + (uint32_t)(row * 36 + word) * 4u;
    }

    float acc[4][4][4];
#pragma unroll
    for (int mt = 0; mt < 4; mt++)
#pragma unroll
        for (int nt = 0; nt < 4; nt++)
#pragma unroll
            for (int e = 0; e < 4; e++) acc[mt][nt][e] = 0.f;

    // Staging helpers: A 256 rows, B 128 rows, 8 16B groups per row
    auto stage_chunk = [&](int chunk, uint32_t sbase) {
        const unsigned* Ap = A + (size_t)chunk * 32;
        const unsigned* Wp = W + (size_t)chunk * 32;
#pragma unroll
        for (int i = 0; i < 4; i++) {
            int c = tid + i * 512;
            int r = c >> 3, col = (c & 7) * 4;
            CP16(sbase + (uint32_t)(r * 36 + col) * 4u, Ap + (size_t)(bm + r) * Eq + col);
        }
#pragma unroll
        for (int i = 0; i < 2; i++) {
            int c = tid + i * 512;
            int r = c >> 3, col = (c & 7) * 4;
            CP16(sbase + BOFF_B + (uint32_t)(r * 36 + col) * 4u, Wp + (size_t)(bn + r) * Eq + col);
        }
        CPC;
    };

    // Prologue: chunks 0 and 1 into stages 0, 1
    stage_chunk(0, base);
    stage_chunk(1, base + STAGE_B);

    int stage = 0;                 // stage of chunk kt
    for (int kt = 0; kt < 32; kt++) {
        if (kt < 31) { CPW(1); } else { CPW(0); }
        __syncthreads();

        if (kt + 2 < 32) {
            int s2 = stage + 2; if (s2 >= 3) s2 -= 3;
            stage_chunk(kt + 2, base + (uint32_t)s2 * STAGE_B);
        }

        const uint32_t so = (uint32_t)stage * STAGE_B;
#pragma unroll
        for (int ks = 0; ks < 4; ks++) {
            const uint32_t kso = so + (uint32_t)ks * 32u;
            unsigned a[4][4];
#pragma unroll
            for (int mt = 0; mt < 4; mt++) {
                ldsm4(a[mt], aaddr[mt] + kso);
                if (RND_A) {
                    a[mt][0] = rnd13(a[mt][0]); a[mt][1] = rnd13(a[mt][1]);
                    a[mt][2] = rnd13(a[mt][2]); a[mt][3] = rnd13(a[mt][3]);
                }
            }
            unsigned bf[2][4];
#pragma unroll
            for (int p = 0; p < 2; p++) {
                ldsm4(bf[p], baddr[p] + kso);
                bf[p][0] = rnd13(bf[p][0]); bf[p][1] = rnd13(bf[p][1]);
                bf[p][2] = rnd13(bf[p][2]); bf[p][3] = rnd13(bf[p][3]);
            }
#pragma unroll
            for (int nt = 0; nt < 4; nt++) {
                unsigned b0 = bf[nt >> 1][(nt & 1) * 2];
                unsigned b1 = bf[nt >> 1][(nt & 1) * 2 + 1];
#pragma unroll
                for (int mt = 0; mt < 4; mt++)
                    mma_tf32(acc[mt][nt], a[mt], b0, b1);
            }
        }
        if (++stage == 3) stage = 0;
    }

    // Epilogue
#pragma unroll
    for (int mt = 0; mt < 4; mt++) {
        int m0 = bm + wm + mt * 16 + g;
#pragma unroll
        for (int nt = 0; nt < 4; nt++) {
            int c = bn + wn + nt * 8 + 2 * tq;
            float bv0 = bias[c], bv1 = bias[c + 1];
            float v0 = acc[mt][nt][0] + bv0;
            float v1 = acc[mt][nt][1] + bv1;
            float v2 = acc[mt][nt][2] + bv0;
            float v3 = acc[mt][nt][3] + bv1;

            if (ROPE) {
                int s0 = m0 & (Sq - 1);
                int s8 = s0 + 8;
                if (c < 1024) {
                    int i = (c >> 1) & 31;
                    float c0 = g_cos[s0 * 32 + i], n0 = g_sin[s0 * 32 + i];
                    float c8 = g_cos[s8 * 32 + i], n8 = g_sin[s8 * 32 + i];
                    uint2 o0, o1;
                    o0.x = f2tf32((v0 * c0 - v1 * n0) * 0.125f);
                    o0.y = f2tf32((v0 * n0 + v1 * c0) * 0.125f);
                    o1.x = f2tf32((v2 * c8 - v3 * n8) * 0.125f);
                    o1.y = f2tf32((v2 * n8 + v3 * c8) * 0.125f);
                    *(uint2*)&g_q[(size_t)m0 * Eq + c]       = o0;
                    *(uint2*)&g_q[(size_t)(m0 + 8) * Eq + c] = o1;
                } else if (c < 1088) {
                    int i = ((c - 1024) >> 1) & 31;
                    float c0 = g_cos[s0 * 32 + i], n0 = g_sin[s0 * 32 + i];
                    float c8 = g_cos[s8 * 32 + i], n8 = g_sin[s8 * 32 + i];
                    uint2 o0, o1;
                    o0.x = f2tf32(v0 * c0 - v1 * n0);
                    o0.y = f2tf32(v0 * n0 + v1 * c0);
                    o1.x = f2tf32(v2 * c8 - v3 * n8);
                    o1.y = f2tf32(v2 * n8 + v3 * c8);
                    *(uint2*)&g_k[(size_t)m0 * 64 + (c - 1024)]       = o0;
                    *(uint2*)&g_k[(size_t)(m0 + 8) * 64 + (c - 1024)] = o1;
                } else {
                    // V: write TRANSPOSED g_vT[b][d][s]
                    int d  = c - 1088;
                    int bb = m0 >> 11;
                    size_t bv = ((size_t)(bb * 64 + d)) * Sq;
                    g_vT[bv + s0]      = f2tf32(v0);
                    g_vT[bv + Sq + s0] = f2tf32(v1);
                    g_vT[bv + s8]      = f2tf32(v2);
                    g_vT[bv + Sq + s8] = f2tf32(v3);
                }
            } else {
                *(float2*)&C[(size_t)m0 * N + c]       = make_float2(v0, v1);
                *(float2*)&C[(size_t)(m0 + 8) * N + c] = make_float2(v2, v3);
            }
        }
    }
}

__global__ __launch_bounds__(512, 1) void gemm_qkv_kernel(const float* __restrict__ x,
                                                          const float* __restrict__ w,
                                                          const float* __restrict__ bias) {
    gemm_body<QKVq, true, true>((const unsigned*)x, (const unsigned*)w, bias, nullptr);
}

__global__ __launch_bounds__(512, 1) void gemm_out_kernel(const float* __restrict__ w,
                                                          const float* __restrict__ bias,
                                                          float* __restrict__ out) {
    gemm_body<Eq, false, false>(g_attn, (const unsigned*)w, bias, out);
}

// ---------------------------------------------------------------------------
// MQA flash attention, cp.async double-buffered, full-ldmatrix fragments.
// Block: 16 seq positions x 16 heads = 256 mma rows; 512 thr, 16 warps.
// K staged [key][d]; V staged TRANSPOSED [d][key] (from g_vT) so both K and
// V fragments load via ldmatrix.x4.
// smem: QP 256x68, Ks 2x64x68, Vs 2x64x68 = 139264 B.
// ---------------------------------------------------------------------------
__global__ __launch_bounds__(512, 1) void attn_tc_kernel() {
    extern __shared__ unsigned sm[];
    unsigned* QP = sm;   // 256*68 (Q, then P as fp32)

    const int b     = blockIdx.y;
    const int qb    = 127 - (int)blockIdx.x;
    const int qbase = qb * 16;
    const int tid   = threadIdx.x;
    const int w     = tid >> 5;
    const int lane  = tid & 31;
    const int g     = lane >> 2;
    const int tq    = lane & 3;
    const int sub   = lane >> 3;

    const uint32_t smb  = smem_u32(sm);
    const uint32_t qp_b = smb;
    const uint32_t ks_b = smb + 256u * 68u * 4u;
    const uint32_t vs_b = ks_b + 2u * 64u * 68u * 4u;

    // A-frag address in QP (Q now, P later)
    const uint32_t qaddr = qp_b +
        (uint32_t)((w * 16 + (sub & 1) * 8 + (lane & 7)) * 68 + (sub >> 1) * 4) * 4u;
    // K / VT fragment addresses (same tile pattern; stride 68)
    uint32_t kaddr[4], vaddr[4];
#pragma unroll
    for (int p = 0; p < 4; p++) {
        int nt   = p * 2 + (sub >> 1);
        int word = (sub & 1) * 4;
        int row  = nt * 8 + (lane & 7);
        kaddr[p] = ks_b + (uint32_t)(row * 68 + word) * 4u;
        vaddr[p] = vs_b + (uint32_t)(row * 68 + word) * 4u;
    }

    // Stage Q: row r = pos_local*16 + head
#pragma unroll
    for (int i = 0; i < 8; i++) {
        int c = tid + i * 512;
        int r = c >> 4, col = (c & 15) * 4;
        const unsigned* src = g_q + (((size_t)(b * Sq + qbase + (r >> 4))) << 10)
                              + ((r & 15) << 6) + col;
        CP16(qp_b + (uint32_t)(r * 68 + col) * 4u, src);
    }
    CPC;

    const int n_tiles = (qbase + 79) >> 6;

    // Stage KV tile 0 (K rows = keys; VT rows = d, cols = keys)
    {
        const unsigned* kp = g_k + ((size_t)(b * Sq)) * 64;
        const unsigned* vp = g_vT + ((size_t)b) * 64 * Sq;
#pragma unroll
        for (int i = 0; i < 2; i++) {
            int c = tid + i * 512;
            int r = c >> 4, col = (c & 15) * 4;
            CP16(ks_b + (uint32_t)(r * 68 + col) * 4u, kp + (size_t)r * 64 + col);
            CP16(vs_b + (uint32_t)(r * 68 + col) * 4u, vp + (size_t)r * Sq + col);
        }
    }
    CPC;
    CPW(1);
    __syncthreads();

    // Preload Q fragments via ldmatrix; QP rows reused as P after
    unsigned qa[8][4];
#pragma unroll
    for (int ks = 0; ks < 8; ks++) ldsm4(qa[ks], qaddr + (uint32_t)ks * 32u);

    float o[8][4];
#pragma unroll
    for (int nt = 0; nt < 8; nt++)
#pragma unroll
        for (int e = 0; e < 4; e++) o[nt][e] = 0.f;
    float mr0 = -1e30f, mr1 = -1e30f, l0 = 0.f, l1 = 0.f;
    const int qpos = qbase + w;
    const int r0   = w * 16 + g;

    for (int kt = 0; kt < n_tiles; kt++) {
        const int buf = kt & 1;
        CPW(0);
        __syncthreads();

        if (kt + 1 < n_tiles) {
            const int kb2 = (kt + 1) * 64;
            const unsigned* kp = g_k + ((size_t)(b * Sq + kb2)) * 64;
            const unsigned* vp = g_vT + ((size_t)b) * 64 * Sq + kb2;
            uint32_t kd = ks_b + (uint32_t)((buf ^ 1) * 4352) * 4u;
            uint32_t vd = vs_b + (uint32_t)((buf ^ 1) * 4352) * 4u;
#pragma unroll
            for (int i = 0; i < 2; i++) {
                int c = tid + i * 512;
                int r = c >> 4, col = (c & 15) * 4;
                CP16(kd + (uint32_t)(r * 68 + col) * 4u, kp + (size_t)r * 64 + col);
                CP16(vd + (uint32_t)(r * 68 + col) * 4u, vp + (size_t)r * Sq + col);
            }
            CPC;
        }

        const uint32_t kbo = (uint32_t)(buf * 4352) * 4u;
        const int kb = kt * 64;

        // S = Q K^T
        float sc[8][4];
#pragma unroll
        for (int nt = 0; nt < 8; nt++)
#pragma unroll
            for (int e = 0; e < 4; e++) sc[nt][e] = 0.f;
#pragma unroll
        for (int ks = 0; ks < 8; ks++) {
            unsigned kf[4][4];
#pragma unroll
            for (int p = 0; p < 4; p++) ldsm4(kf[p], kaddr[p] + kbo + (uint32_t)ks * 32u);
#pragma unroll
            for (int nt = 0; nt < 8; nt++) {
                unsigned b0 = kf[nt >> 1][(nt & 1) * 2];
                unsigned b1 = kf[nt >> 1][(nt & 1) * 2 + 1];
                mma_tf32(sc[nt], qa[ks], b0, b1);
            }
        }

        // Causal mask
        if (kb + 63 > qpos) {
#pragma unroll
            for (int nt = 0; nt < 8; nt++) {
                int key = kb + nt * 8 + 2 * tq;
                if (key > qpos)     { sc[nt][0] = -1e30f; sc[nt][2] = -1e30f; }
                if (key + 1 > qpos) { sc[nt][1] = -1e30f; sc[nt][3] = -1e30f; }
            }
        }

        // Online softmax
        float mx0 = -1e30f, mx1 = -1e30f;
#pragma unroll
        for (int nt = 0; nt < 8; nt++) {
            mx0 = fmaxf(mx0, fmaxf(sc[nt][0], sc[nt][1]));
            mx1 = fmaxf(mx1, fmaxf(sc[nt][2], sc[nt][3]));
        }
        mx0 = fmaxf(mx0, __shfl_xor_sync(0xFFFFFFFFu, mx0, 1));
        mx0 = fmaxf(mx0, __shfl_xor_sync(0xFFFFFFFFu, mx0, 2));
        mx1 = fmaxf(mx1, __shfl_xor_sync(0xFFFFFFFFu, mx1, 1));
        mx1 = fmaxf(mx1, __shfl_xor_sync(0xFFFFFFFFu, mx1, 2));

        float mn0 = fmaxf(mr0, mx0);
        float mn1 = fmaxf(mr1, mx1);
        float corr0 = __expf(mr0 - mn0);
        float corr1 = __expf(mr1 - mn1);
        float sum0 = 0.f, sum1 = 0.f;
#pragma unroll
        for (int nt = 0; nt < 8; nt++) {
            sc[nt][0] = __expf(sc[nt][0] - mn0);
            sc[nt][1] = __expf(sc[nt][1] - mn0);
            sc[nt][2] = __expf(sc[nt][2] - mn1);
            sc[nt][3] = __expf(sc[nt][3] - mn1);
            sum0 += sc[nt][0] + sc[nt][1];
            sum1 += sc[nt][2] + sc[nt][3];
        }
        sum0 += __shfl_xor_sync(0xFFFFFFFFu, sum0, 1);
        sum0 += __shfl_xor_sync(0xFFFFFFFFu, sum0, 2);
        sum1 += __shfl_xor_sync(0xFFFFFFFFu, sum1, 1);
        sum1 += __shfl_xor_sync(0xFFFFFFFFu, sum1, 2);

        mr0 = mn0; mr1 = mn1;
        l0 = l0 * corr0 + sum0;
        l1 = l1 * corr1 + sum1;
#pragma unroll
        for (int nt = 0; nt < 8; nt++) {
            o[nt][0] *= corr0; o[nt][1] *= corr0;
            o[nt][2] *= corr1; o[nt][3] *= corr1;
        }

        // Store P (raw fp32; rounded at fragment load)
        float* QPf = (float*)QP;
#pragma unroll
        for (int nt = 0; nt < 8; nt++) {
            *(float2*)&QPf[r0 * 68 + nt * 8 + 2 * tq]       = make_float2(sc[nt][0], sc[nt][1]);
            *(float2*)&QPf[(r0 + 8) * 68 + nt * 8 + 2 * tq] = make_float2(sc[nt][2], sc[nt][3]);
        }
        __syncwarp();

        // O += P V   (V fragments via ldmatrix from transposed tile)
#pragma unroll
        for (int ks = 0; ks < 8; ks++) {
            unsigned pa[4];
            ldsm4(pa, qaddr + (uint32_t)ks * 32u);
            pa[0] = rnd13(pa[0]); pa[1] = rnd13(pa[1]);
            pa[2] = rnd13(pa[2]); pa[3] = rnd13(pa[3]);
            unsigned vf[4][4];
#pragma unroll
            for (int p = 0; p < 4; p++) ldsm4(vf[p], vaddr[p] + kbo + (uint32_t)ks * 32u);
#pragma unroll
            for (int nt = 0; nt < 8; nt++) {
                unsigned b0 = vf[nt >> 1][(nt & 1) * 2];
                unsigned b1 = vf[nt >> 1][(nt & 1) * 2 + 1];
                mma_tf32(o[nt], pa, b0, b1);
            }
        }
    }

    // Epilogue: normalize, write tf32 to g_attn[b][qpos][head*64+d]
    float inv0 = 1.f / l0;
    float inv1 = 1.f / l1;
    unsigned* dst0 = g_attn + (((size_t)(b * Sq + qpos)) << 10) + (g << 6);
    unsigned* dst1 = g_attn + (((size_t)(b * Sq + qpos)) << 10) + ((g + 8) << 6);
#pragma unroll
    for (int nt = 0; nt < 8; nt++) {
        int c = nt * 8 + 2 * tq;
        uint2 a0, a1;
        a0.x = f2tf32(o[nt][0] * inv0); a0.y = f2tf32(o[nt][1] * inv0);
        a1.x = f2tf32(o[nt][2] * inv1); a1.y = f2tf32(o[nt][3] * inv1);
        *(uint2*)&dst0[c] = a0;
        *(uint2*)&dst1[c] = a1;
    }
}

// ---------------------------------------------------------------------------
extern "C" void kernel_launch(void* const* d_in, const int* in_sizes, int n_in,
                              void* d_out, int out_size) {
    const float* x     = (const float*)d_in[0];
    const float* qkv_w = (const float*)d_in[1];
    const float* qkv_b = (const float*)d_in[2];
    const float* out_w = (const float*)d_in[3];
    const float* out_b = (const float*)d_in[4];
    float* out = (float*)d_out;

    const int GEMM_SMEM = 3 * 55296;                                   // 165888
    const int ATTN_SMEM = (256 * 68 + 2 * 64 * 68 + 2 * 64 * 68) * 4;  // 139264

    cudaFuncSetAttribute(gemm_qkv_kernel, cudaFuncAttributeMaxDynamicSharedMemorySize, GEMM_SMEM);
    cudaFuncSetAttribute(gemm_out_kernel, cudaFuncAttributeMaxDynamicSharedMemorySize, GEMM_SMEM);
    cudaFuncSetAttribute(attn_tc_kernel,  cudaFuncAttributeMaxDynamicSharedMemorySize, ATTN_SMEM);

    // 1. RoPE tables (must precede QKV GEMM epilogue)
    rope_tables_kernel<<<(Sq * 32 + 255) / 256, 256>>>();

    // 2. QKV projection + bias + RoPE + scale + tf32 pack (fused epilogue)
    gemm_qkv_kernel<<<dim3(QKVq / 128, (Bq * Sq) / 256), 512, GEMM_SMEM>>>(x, qkv_w, qkv_b);

    // 3. Causal MQA flash attention -> g_attn (tf32)
    attn_tc_kernel<<<dim3(Sq / 16, Bq), 512, ATTN_SMEM>>>();

    // 4. Output projection + bias -> out (fp32)
    gemm_out_kernel<<<dim3(Eq / 128, (Bq * Sq) / 256), 512, GEMM_SMEM>>>(out_w, out_b, out);
}